// round 1
// baseline (speedup 1.0000x reference)
#include <cuda_runtime.h>
#include <cstdint>

#define NN 20000
#define NE 320000
#define ET 340000   /* NE + NN self loops */
#define F1 256
#define HD 512      /* 8 heads * 64 */
#define NH 8
#define DH 64
#define NC 16
#define NEG 0.2f

/* ----------------------------- device scratch ---------------------------- */
__device__ float g_xl1[NN * HD];
__device__ float g_xr1[NN * HD];
__device__ float g_h  [NN * HD];
__device__ float g_xl2[NN * NC];
__device__ float g_xr2[NN * NC];
__device__ int   g_deg[NN];
__device__ int   g_rowptr[NN + 1];
__device__ int   g_wp[NN];
__device__ int   g_col[ET];
__device__ int   g_is64;

/* --------------------------- small device helpers ------------------------ */
__device__ __forceinline__ float lrelu(float x) { return x > 0.f ? x : NEG * x; }

__device__ __forceinline__ unsigned long long pk2(float x, float y) {
    unsigned long long r;
    asm("mov.b64 %0, {%1, %2};" : "=l"(r)
        : "r"(__float_as_uint(x)), "r"(__float_as_uint(y)));
    return r;
}
__device__ __forceinline__ void fma2(unsigned long long& c,
                                     unsigned long long a, unsigned long long b) {
    asm("fma.rn.f32x2 %0, %1, %2, %0;" : "+l"(c) : "l"(a), "l"(b));
}
__device__ __forceinline__ float2 upk2(unsigned long long v) {
    unsigned lo, hi;
    asm("mov.b64 {%0, %1}, %2;" : "=r"(lo), "=r"(hi) : "l"(v));
    return make_float2(__uint_as_float(lo), __uint_as_float(hi));
}

/* edge_index element fetch honoring detected dtype */
__device__ __forceinline__ int edge_val(const void* ei, int idx) {
    if (g_is64) return (int)(((const long long*)ei)[idx]);
    return ((const int*)ei)[idx];
}

/* --------------------------- dtype detection ----------------------------- */
/* If edge_index is int64, every odd 32-bit word of the first 1024 elements is
   the (zero) high half (values < 20000). If int32, those words are random
   node ids — the chance all 1024 are zero is ~0. */
__global__ void k_detect(const int* __restrict__ ei32) {
    __shared__ int s;
    if (threadIdx.x == 0) s = 0;
    __syncthreads();
    int v = ei32[threadIdx.x * 2 + 1];
    if (v != 0) atomicOr(&s, 1);
    __syncthreads();
    if (threadIdx.x == 0) g_is64 = (s == 0) ? 1 : 0;
}

/* ------------------------------- CSR build ------------------------------- */
__global__ void k_zero_deg() {
    int i = blockIdx.x * blockDim.x + threadIdx.x;
    if (i < NN) g_deg[i] = 0;
}

__global__ void k_hist(const void* __restrict__ ei) {
    int i = blockIdx.x * blockDim.x + threadIdx.x;
    if (i >= ET) return;
    int dst = (i < NE) ? edge_val(ei, NE + i) : (i - NE);
    atomicAdd(&g_deg[dst], 1);
}

__global__ void k_scan() {   /* single block, 1024 threads */
    __shared__ int sh[1024];
    __shared__ int carry_sh;
    int tid = threadIdx.x;
    if (tid == 0) carry_sh = 0;
    __syncthreads();
    for (int base = 0; base < NN; base += 1024) {
        int i = base + tid;
        int v = (i < NN) ? g_deg[i] : 0;
        sh[tid] = v;
        __syncthreads();
        #pragma unroll
        for (int off = 1; off < 1024; off <<= 1) {
            int t = (tid >= off) ? sh[tid - off] : 0;
            __syncthreads();
            sh[tid] += t;
            __syncthreads();
        }
        int incl = sh[tid];
        int c = carry_sh;
        if (i < NN) {
            int excl = c + incl - v;
            g_rowptr[i] = excl;
            g_wp[i] = excl;
            if (i == NN - 1) g_rowptr[NN] = c + incl;
        }
        __syncthreads();
        if (tid == 1023) carry_sh = c + sh[1023];
        __syncthreads();
    }
}

__global__ void k_scatter(const void* __restrict__ ei) {
    int i = blockIdx.x * blockDim.x + threadIdx.x;
    if (i >= ET) return;
    int src, dst;
    if (i < NE) { src = edge_val(ei, i); dst = edge_val(ei, NE + i); }
    else        { src = i - NE; dst = i - NE; }
    int pos = atomicAdd(&g_wp[dst], 1);
    g_col[pos] = src;
}

/* -------------------- SGEMM with packed fp32x2 FMA ----------------------- */
/* C{0,1}[M,N] = A[M,K] @ W{0,1}[K,N] + b{0,1};  blockIdx.z selects pair.    */
#define BM 128
#define BN 64
#define BK 16

__global__ void __launch_bounds__(256)
k_sgemm2(const float* __restrict__ A, int M, int N, int K,
         const float* __restrict__ W0, const float* __restrict__ b0, float* __restrict__ C0,
         const float* __restrict__ W1, const float* __restrict__ b1, float* __restrict__ C1)
{
    const float* W    = blockIdx.z ? W1 : W0;
    const float* bias = blockIdx.z ? b1 : b0;
    float*       C    = blockIdx.z ? C1 : C0;

    __shared__ __align__(16) float As[BK][BM];
    __shared__ __align__(16) float Bs[BK][BN];

    int tid = threadIdx.x;
    int bm = blockIdx.x * BM;
    int bn = blockIdx.y * BN;
    int ar = tid >> 2;            /* 0..63  */
    int ac = (tid & 3) << 2;      /* 0..12  */
    int br = tid >> 4;            /* 0..15  */
    int bc = (tid & 15) << 2;     /* 0..60  */
    int trow = (tid >> 4) << 3;   /* 0..120 */
    int tcol = (tid & 15) << 2;   /* 0..60  */

    unsigned long long acc[4][4];
    #pragma unroll
    for (int i = 0; i < 4; i++)
        #pragma unroll
        for (int j = 0; j < 4; j++) acc[i][j] = 0ull;

    for (int k0 = 0; k0 < K; k0 += BK) {
        #pragma unroll
        for (int rr = 0; rr < 2; rr++) {
            int m = bm + ar + rr * 64;
            float4 v = make_float4(0.f, 0.f, 0.f, 0.f);
            if (m < M)
                v = *reinterpret_cast<const float4*>(A + (size_t)m * K + k0 + ac);
            As[ac + 0][ar + rr * 64] = v.x;
            As[ac + 1][ar + rr * 64] = v.y;
            As[ac + 2][ar + rr * 64] = v.z;
            As[ac + 3][ar + rr * 64] = v.w;
        }
        *reinterpret_cast<float4*>(&Bs[br][bc]) =
            *reinterpret_cast<const float4*>(W + (size_t)(k0 + br) * N + bn + bc);
        __syncthreads();

        #pragma unroll
        for (int kk = 0; kk < BK; kk++) {
            ulonglong2 a01 = *reinterpret_cast<const ulonglong2*>(&As[kk][trow]);
            ulonglong2 a23 = *reinterpret_cast<const ulonglong2*>(&As[kk][trow + 4]);
            float4 bv = *reinterpret_cast<const float4*>(&Bs[kk][tcol]);
            unsigned long long bb[4];
            bb[0] = pk2(bv.x, bv.x);
            bb[1] = pk2(bv.y, bv.y);
            bb[2] = pk2(bv.z, bv.z);
            bb[3] = pk2(bv.w, bv.w);
            unsigned long long ap[4] = {a01.x, a01.y, a23.x, a23.y};
            #pragma unroll
            for (int i = 0; i < 4; i++)
                #pragma unroll
                for (int j = 0; j < 4; j++)
                    fma2(acc[i][j], ap[i], bb[j]);
        }
        __syncthreads();
    }

    float4 bias4 = *reinterpret_cast<const float4*>(bias + bn + tcol);
    #pragma unroll
    for (int i = 0; i < 4; i++) {
        float2 f0 = upk2(acc[i][0]);
        float2 f1 = upk2(acc[i][1]);
        float2 f2 = upk2(acc[i][2]);
        float2 f3 = upk2(acc[i][3]);
        int m0 = bm + trow + i * 2;
        if (m0 < M) {
            float4 o = make_float4(f0.x + bias4.x, f1.x + bias4.y,
                                   f2.x + bias4.z, f3.x + bias4.w);
            *reinterpret_cast<float4*>(C + (size_t)m0 * N + bn + tcol) = o;
        }
        if (m0 + 1 < M) {
            float4 o = make_float4(f0.y + bias4.x, f1.y + bias4.y,
                                   f2.y + bias4.z, f3.y + bias4.w);
            *reinterpret_cast<float4*>(C + (size_t)(m0 + 1) * N + bn + tcol) = o;
        }
    }
}

/* -------------------- layer-1 GATv2 (flash-style softmax) ---------------- */
/* one block (128 threads) per node; thread t owns dims [4t, 4t+4) i.e.
   head = t/16, within-head dims (t%16)*4.. ; online softmax over in-edges. */
__global__ void __launch_bounds__(128)
k_gat1(const float* __restrict__ xl, const float* __restrict__ xr,
       const float* __restrict__ att, const float* __restrict__ bias,
       float* __restrict__ hout)
{
    int node = blockIdx.x;
    int tid = threadIdx.x;

    float4 xrv = reinterpret_cast<const float4*>(xr + (size_t)node * HD)[tid];
    float4 av  = reinterpret_cast<const float4*>(att)[tid];
    float4 bv  = reinterpret_cast<const float4*>(bias)[tid];

    int jb = g_rowptr[node], je = g_rowptr[node + 1];

    float m = -1e30f, s = 0.f;
    float4 acc = make_float4(0.f, 0.f, 0.f, 0.f);

    const float4* xlp = reinterpret_cast<const float4*>(xl);
    float4 xlv = make_float4(0.f, 0.f, 0.f, 0.f);
    if (jb < je) {
        int src0 = g_col[jb];
        xlv = xlp[(size_t)src0 * 128 + tid];
    }
    for (int j = jb; j < je; j++) {
        float4 cur = xlv;
        if (j + 1 < je) {
            int ns = g_col[j + 1];
            xlv = xlp[(size_t)ns * 128 + tid];
        }
        float4 t;
        t.x = lrelu(cur.x + xrv.x);
        t.y = lrelu(cur.y + xrv.y);
        t.z = lrelu(cur.z + xrv.z);
        t.w = lrelu(cur.w + xrv.w);
        float e = t.x * av.x + t.y * av.y + t.z * av.z + t.w * av.w;
        e += __shfl_down_sync(0xffffffffu, e, 8, 16);
        e += __shfl_down_sync(0xffffffffu, e, 4, 16);
        e += __shfl_down_sync(0xffffffffu, e, 2, 16);
        e += __shfl_down_sync(0xffffffffu, e, 1, 16);
        e  = __shfl_sync(0xffffffffu, e, 0, 16);

        float nm = fmaxf(m, e);
        float sc = __expf(m - nm);
        float w  = __expf(e - nm);
        s = s * sc + w;
        acc.x = acc.x * sc + w * cur.x;
        acc.y = acc.y * sc + w * cur.y;
        acc.z = acc.z * sc + w * cur.z;
        acc.w = acc.w * sc + w * cur.w;
        m = nm;
    }
    float inv = 1.f / s;
    float4 o;
    o.x = fmaxf(acc.x * inv + bv.x, 0.f);
    o.y = fmaxf(acc.y * inv + bv.y, 0.f);
    o.z = fmaxf(acc.z * inv + bv.z, 0.f);
    o.w = fmaxf(acc.w * inv + bv.w, 0.f);
    reinterpret_cast<float4*>(hout + (size_t)node * HD)[tid] = o;
}

/* ----------------- layer-2 linear: xl2 = h@Wl2+b, xr2 = h@Wr2+b ----------- */
/* one warp per node; lane owns k-chunk [lane*16, lane*16+16), 32 partials,
   butterfly reduce, lane 0 stores. */
__global__ void __launch_bounds__(256)
k_lin2(const float* __restrict__ h,
       const float* __restrict__ Wl, const float* __restrict__ bl,
       const float* __restrict__ Wr, const float* __restrict__ br_,
       float* __restrict__ xl2, float* __restrict__ xr2)
{
    int node = blockIdx.x * 8 + (threadIdx.x >> 5);
    if (node >= NN) return;
    int lane = threadIdx.x & 31;

    float hs[16];
    const float4* hr = reinterpret_cast<const float4*>(h + (size_t)node * HD) + lane * 4;
    #pragma unroll
    for (int i = 0; i < 4; i++) {
        float4 v = hr[i];
        hs[i * 4 + 0] = v.x; hs[i * 4 + 1] = v.y;
        hs[i * 4 + 2] = v.z; hs[i * 4 + 3] = v.w;
    }

    float p[32];
    #pragma unroll
    for (int c = 0; c < 32; c++) p[c] = 0.f;

    #pragma unroll
    for (int j = 0; j < 16; j++) {
        int k = lane * 16 + j;
        float hk = hs[j];
        const float4* wl = reinterpret_cast<const float4*>(Wl) + k * 4;
        const float4* wr = reinterpret_cast<const float4*>(Wr) + k * 4;
        #pragma unroll
        for (int q = 0; q < 4; q++) {
            float4 w = wl[q];
            p[q * 4 + 0] += hk * w.x; p[q * 4 + 1] += hk * w.y;
            p[q * 4 + 2] += hk * w.z; p[q * 4 + 3] += hk * w.w;
        }
        #pragma unroll
        for (int q = 0; q < 4; q++) {
            float4 w = wr[q];
            p[16 + q * 4 + 0] += hk * w.x; p[16 + q * 4 + 1] += hk * w.y;
            p[16 + q * 4 + 2] += hk * w.z; p[16 + q * 4 + 3] += hk * w.w;
        }
    }
    #pragma unroll
    for (int off = 16; off; off >>= 1)
        #pragma unroll
        for (int c = 0; c < 32; c++)
            p[c] += __shfl_xor_sync(0xffffffffu, p[c], off);

    if (lane == 0) {
        #pragma unroll
        for (int c = 0; c < 16; c++) {
            xl2[(size_t)node * NC + c] = p[c] + bl[c];
            xr2[(size_t)node * NC + c] = p[16 + c] + br_[c];
        }
    }
}

/* --------------------- layer-2 GATv2 (H=1, D=16) -------------------------- */
/* 16-lane group per node; lane owns one output dim. */
__global__ void __launch_bounds__(256)
k_gat2(const float* __restrict__ xl, const float* __restrict__ xr,
       const float* __restrict__ att, const float* __restrict__ bias,
       float* __restrict__ out)
{
    int node = blockIdx.x * 16 + (threadIdx.x >> 4);
    int lane = threadIdx.x & 15;
    if (node >= NN) return;

    float xrv = xr[(size_t)node * NC + lane];
    float av  = att[lane];

    int jb = g_rowptr[node], je = g_rowptr[node + 1];
    float m = -1e30f, s = 0.f, acc = 0.f;

    for (int j = jb; j < je; j++) {
        int src = g_col[j];
        float xlv = xl[(size_t)src * NC + lane];
        float t = lrelu(xlv + xrv);
        float e = t * av;
        e += __shfl_down_sync(0xffffffffu, e, 8, 16);
        e += __shfl_down_sync(0xffffffffu, e, 4, 16);
        e += __shfl_down_sync(0xffffffffu, e, 2, 16);
        e += __shfl_down_sync(0xffffffffu, e, 1, 16);
        e  = __shfl_sync(0xffffffffu, e, 0, 16);

        float nm = fmaxf(m, e);
        float sc = __expf(m - nm);
        float w  = __expf(e - nm);
        s = s * sc + w;
        acc = acc * sc + w * xlv;
        m = nm;
    }
    out[(size_t)node * NC + lane] = acc / s + bias[lane];
}

/* ------------------------------- launch ---------------------------------- */
extern "C" void kernel_launch(void* const* d_in, const int* in_sizes, int n_in,
                              void* d_out, int out_size)
{
    const float* x     = (const float*)d_in[0];
    const void*  ei    = d_in[1];
    const float* W_l1  = (const float*)d_in[2];
    const float* b_l1  = (const float*)d_in[3];
    const float* W_r1  = (const float*)d_in[4];
    const float* b_r1  = (const float*)d_in[5];
    const float* att1  = (const float*)d_in[6];
    const float* bias1 = (const float*)d_in[7];
    const float* W_l2  = (const float*)d_in[8];
    const float* b_l2  = (const float*)d_in[9];
    const float* W_r2  = (const float*)d_in[10];
    const float* b_r2  = (const float*)d_in[11];
    const float* att2  = (const float*)d_in[12];
    const float* bias2 = (const float*)d_in[13];
    float* out = (float*)d_out;

    float *xl1, *xr1, *h, *xl2, *xr2;
    cudaGetSymbolAddress((void**)&xl1, g_xl1);
    cudaGetSymbolAddress((void**)&xr1, g_xr1);
    cudaGetSymbolAddress((void**)&h,   g_h);
    cudaGetSymbolAddress((void**)&xl2, g_xl2);
    cudaGetSymbolAddress((void**)&xr2, g_xr2);

    k_detect<<<1, 1024>>>((const int*)ei);
    k_zero_deg<<<(NN + 255) / 256, 256>>>();
    k_hist<<<(ET + 255) / 256, 256>>>(ei);
    k_scan<<<1, 1024>>>();
    k_scatter<<<(ET + 255) / 256, 256>>>(ei);

    dim3 g1((NN + BM - 1) / BM, HD / BN, 2);
    k_sgemm2<<<g1, 256>>>(x, NN, HD, F1, W_l1, b_l1, xl1, W_r1, b_r1, xr1);

    k_gat1<<<NN, 128>>>(xl1, xr1, att1, bias1, h);

    k_lin2<<<(NN + 7) / 8, 256>>>(h, W_l2, b_l2, W_r2, b_r2, xl2, xr2);

    k_gat2<<<(NN + 15) / 16, 256>>>(xl2, xr2, att2, bias2, out);
}